// round 1
// baseline (speedup 1.0000x reference)
#include <cuda_runtime.h>
#include <cuda_fp16.h>
#include <cstdint>

#define N_TOK 16384
#define DIM   1024
#define HID   4096
#define NEXP  8
#define CAP   8192
#define RBLK  64

// ---------------- scratch (static device globals; no allocation) ----------------
__device__ __half g_W1h[NEXP*DIM*HID];        // 64 MB
__device__ __half g_W2h[NEXP*HID*DIM];        // 64 MB
__device__ __half g_hbuf[268435456];          // [E*CAP, HID] fp16, 512 MB
__device__ float  g_outs[67108864];           // [E*CAP, DIM] fp32, 256 MB
__device__ int    g_sel[NEXP*CAP];
__device__ int    g_slot[N_TOK*2];
__device__ float  g_tw[N_TOK*2];
__device__ int    g_ti[N_TOK*2];
__device__ float  g_pspart[RBLK*NEXP];
__device__ int    g_counts[NEXP];
__device__ int    g_cnt[NEXP];

// ---------------- helpers ----------------
__device__ __forceinline__ uint32_t smaddr(const void* p){
    return (uint32_t)__cvta_generic_to_shared(p);
}
__device__ __forceinline__ void ldmA4(uint32_t a[4], const void* p){
    uint32_t addr = smaddr(p);
    asm volatile("ldmatrix.sync.aligned.m8n8.x4.shared.b16 {%0,%1,%2,%3}, [%4];"
        : "=r"(a[0]), "=r"(a[1]), "=r"(a[2]), "=r"(a[3]) : "r"(addr));
}
__device__ __forceinline__ void ldmB2(uint32_t b[2], const void* p){
    uint32_t addr = smaddr(p);
    asm volatile("ldmatrix.sync.aligned.m8n8.x2.trans.shared.b16 {%0,%1}, [%2];"
        : "=r"(b[0]), "=r"(b[1]) : "r"(addr));
}
__device__ __forceinline__ void mma16816(float c[4], const uint32_t a[4], const uint32_t b[2]){
    asm volatile("mma.sync.aligned.m16n8k16.row.col.f32.f16.f16.f32 "
        "{%0,%1,%2,%3}, {%4,%5,%6,%7}, {%8,%9}, {%0,%1,%2,%3};"
        : "+f"(c[0]), "+f"(c[1]), "+f"(c[2]), "+f"(c[3])
        : "r"(a[0]), "r"(a[1]), "r"(a[2]), "r"(a[3]), "r"(b[0]), "r"(b[1]));
}

// ---------------- init ----------------
__global__ void init_kernel(){
    if(threadIdx.x < NEXP) g_counts[threadIdx.x] = 0;
}

// ---------------- router: logits -> softmax -> top2 ----------------
__global__ void __launch_bounds__(256) router_kernel(const float* __restrict__ x,
                                                     const float* __restrict__ Wr,
                                                     const float* __restrict__ br){
    __shared__ float sW[DIM*NEXP];
    __shared__ float sPS[NEXP];
    const int tid = threadIdx.x;
    for(int i = tid; i < DIM*NEXP; i += 256) sW[i] = Wr[i];
    if(tid < NEXP) sPS[tid] = 0.f;
    __syncthreads();

    const int n = blockIdx.x*256 + tid;
    float acc[NEXP];
    #pragma unroll
    for(int e=0;e<NEXP;e++) acc[e] = br[e];
    const float4* xr = reinterpret_cast<const float4*>(x + (size_t)n*DIM);
    for(int d4 = 0; d4 < DIM/4; d4++){
        float4 v = xr[d4];
        const float* w = &sW[d4*4*NEXP];
        #pragma unroll
        for(int e=0;e<NEXP;e++)
            acc[e] += v.x*w[e] + v.y*w[NEXP+e] + v.z*w[2*NEXP+e] + v.w*w[3*NEXP+e];
    }
    float m = acc[0];
    #pragma unroll
    for(int e=1;e<NEXP;e++) m = fmaxf(m, acc[e]);
    float p[NEXP]; float s = 0.f;
    #pragma unroll
    for(int e=0;e<NEXP;e++){ p[e] = expf(acc[e]-m); s += p[e]; }
    float inv = 1.f/s;
    #pragma unroll
    for(int e=0;e<NEXP;e++) p[e] *= inv;

    int i0 = 0;
    #pragma unroll
    for(int e=1;e<NEXP;e++) if(p[e] > p[i0]) i0 = e;
    int i1 = -1;
    #pragma unroll
    for(int e=0;e<NEXP;e++) if(e != i0 && (i1 < 0 || p[e] > p[i1])) i1 = e;

    g_ti[2*n]   = i0;  g_ti[2*n+1]   = i1;
    g_tw[2*n]   = p[i0]; g_tw[2*n+1] = p[i1];
    g_slot[2*n] = -1;  g_slot[2*n+1] = -1;
    atomicAdd(&g_counts[i0], 1);
    atomicAdd(&g_counts[i1], 1);

    #pragma unroll
    for(int e=0;e<NEXP;e++){
        float v = p[e];
        for(int off=16; off; off >>= 1) v += __shfl_down_sync(0xffffffffu, v, off);
        if((tid & 31) == 0) atomicAdd(&sPS[e], v);
    }
    __syncthreads();
    if(tid < NEXP) g_pspart[blockIdx.x*NEXP + tid] = sPS[tid];
}

// ---------------- per-expert capacity scan ----------------
__global__ void __launch_bounds__(256) scan_kernel(){
    const int e = blockIdx.x;
    const int tid = threadIdx.x;
    __shared__ int sS[256];
    int base = 0;
    for(int c = 0; c < N_TOK/256; c++){
        int n = c*256 + tid;
        int i0 = g_ti[2*n], i1 = g_ti[2*n+1];
        int kk = (i0 == e) ? 0 : ((i1 == e) ? 1 : -1);
        int flag = (kk >= 0) ? 1 : 0;
        sS[tid] = flag; __syncthreads();
        for(int off = 1; off < 256; off <<= 1){
            int v = (tid >= off) ? sS[tid-off] : 0;
            __syncthreads();
            sS[tid] += v; __syncthreads();
        }
        int pos = base + sS[tid] - flag;
        if(flag && pos < CAP){
            g_sel[e*CAP + pos] = n;
            g_slot[2*n + kk] = e*CAP + pos;
        }
        base += sS[255];
        __syncthreads();
    }
    int cnt = min(base, CAP);
    if(tid == 0) g_cnt[e] = cnt;
    for(int i = cnt + tid; i < CAP; i += 256) g_sel[e*CAP + i] = 0;
}

// ---------------- fp32 -> fp16 weight conversion ----------------
__global__ void convert_kernel(const float4* __restrict__ src, int which){
    __half2* dst = reinterpret_cast<__half2*>(which == 0 ? g_W1h : g_W2h);
    const int n4 = NEXP*DIM*HID/4;
    for(int i = blockIdx.x*blockDim.x + threadIdx.x; i < n4; i += gridDim.x*blockDim.x){
        float4 v = src[i];
        dst[2*i]   = __floats2half2_rn(v.x, v.y);
        dst[2*i+1] = __floats2half2_rn(v.z, v.w);
    }
}

// ---------------- grouped GEMM (LAYER=1: gather+relu->h ; LAYER=2: ->outs) ----------------
template<int LAYER>
__global__ void __launch_bounds__(256,1) gemm_kernel(const float* __restrict__ A32,
                                                     const float* __restrict__ bias){
    constexpr int BM = 128, BN = 128, BK = 32;
    constexpr int KDIM = (LAYER == 1) ? DIM : HID;
    constexpr int NDIM = (LAYER == 1) ? HID : DIM;
    constexpr int KT = KDIM / BK;

    const int e  = blockIdx.z;
    const int m0 = blockIdx.y * BM;
    const int n0 = blockIdx.x * BN;
    if(m0 >= g_cnt[e]) return;

    __shared__ __half As[2][BM][BK+8];
    __shared__ __half Bs[2][BK][BN+8];
    __shared__ int sRow[BM];

    const int tid = threadIdx.x;
    if(LAYER == 1){
        if(tid < BM) sRow[tid] = g_sel[e*CAP + m0 + tid];
    }
    __syncthreads();

    const __half* __restrict__ Wp = ((LAYER == 1) ? g_W1h : g_W2h) + (size_t)e*KDIM*NDIM;
    const __half* __restrict__ Hp = g_hbuf + (size_t)(e*CAP + m0)*HID;

    float4 aF[4];
    uint4  aH[2];
    uint4  bH[2];

    const int lane  = tid & 31;
    const int wid   = tid >> 5;
    const int wm    = wid & 1;
    const int wn    = wid >> 1;
    const int lrow  = lane & 15;
    const int lcol8 = (lane >> 4) * 8;

    float acc[4][4][4];
    #pragma unroll
    for(int mi=0;mi<4;mi++)
        #pragma unroll
        for(int ni=0;ni<4;ni++)
            #pragma unroll
            for(int q=0;q<4;q++) acc[mi][ni][q] = 0.f;

    auto loadA = [&](int kt){
        const int k0 = kt*BK;
        if(LAYER == 1){
            #pragma unroll
            for(int p=0;p<4;p++){
                int idx = tid + p*256;
                int r = idx >> 3;
                int c = (idx & 7) * 4;
                aF[p] = *reinterpret_cast<const float4*>(A32 + (size_t)sRow[r]*DIM + k0 + c);
            }
        }else{
            #pragma unroll
            for(int p=0;p<2;p++){
                int idx = tid + p*256;
                int r = idx >> 2;
                int c = (idx & 3) * 8;
                aH[p] = *reinterpret_cast<const uint4*>(Hp + (size_t)r*HID + k0 + c);
            }
        }
    };
    auto loadB = [&](int kt){
        const int k0 = kt*BK;
        #pragma unroll
        for(int p=0;p<2;p++){
            int idx = tid + p*256;
            int r = idx >> 4;
            int c = (idx & 15) * 8;
            bH[p] = *reinterpret_cast<const uint4*>(Wp + (size_t)(k0+r)*NDIM + n0 + c);
        }
    };
    auto stoA = [&](int buf){
        if(LAYER == 1){
            #pragma unroll
            for(int p=0;p<4;p++){
                int idx = tid + p*256;
                int r = idx >> 3;
                int c = (idx & 7) * 4;
                __half2* d = reinterpret_cast<__half2*>(&As[buf][r][c]);
                d[0] = __floats2half2_rn(aF[p].x, aF[p].y);
                d[1] = __floats2half2_rn(aF[p].z, aF[p].w);
            }
        }else{
            #pragma unroll
            for(int p=0;p<2;p++){
                int idx = tid + p*256;
                int r = idx >> 2;
                int c = (idx & 3) * 8;
                *reinterpret_cast<uint4*>(&As[buf][r][c]) = aH[p];
            }
        }
    };
    auto stoB = [&](int buf){
        #pragma unroll
        for(int p=0;p<2;p++){
            int idx = tid + p*256;
            int r = idx >> 4;
            int c = (idx & 15) * 8;
            *reinterpret_cast<uint4*>(&Bs[buf][r][c]) = bH[p];
        }
    };
    auto compute = [&](int buf){
        #pragma unroll
        for(int ks=0;ks<2;ks++){
            uint32_t a[4][4];
            uint32_t b[4][2];
            #pragma unroll
            for(int mi=0;mi<4;mi++)
                ldmA4(a[mi], &As[buf][wm*64 + mi*16 + lrow][ks*16 + lcol8]);
            #pragma unroll
            for(int ni=0;ni<4;ni++)
                ldmB2(b[ni], &Bs[buf][ks*16 + lrow][wn*32 + ni*8]);
            #pragma unroll
            for(int mi=0;mi<4;mi++)
                #pragma unroll
                for(int ni=0;ni<4;ni++)
                    mma16816(acc[mi][ni], a[mi], b[ni]);
        }
    };

    loadA(0); loadB(0);
    stoA(0);  stoB(0);
    __syncthreads();
    int buf = 0;
    for(int kt = 0; kt < KT; kt++){
        if(kt + 1 < KT){ loadA(kt+1); loadB(kt+1); }
        compute(buf);
        if(kt + 1 < KT){
            stoA(buf^1); stoB(buf^1);
            __syncthreads();
            buf ^= 1;
        }
    }

    const int g = lane >> 2;
    const int t = lane & 3;
    #pragma unroll
    for(int mi=0;mi<4;mi++){
        #pragma unroll
        for(int ni=0;ni<4;ni++){
            int col = n0 + wn*32 + ni*8 + t*2;
            float bv0 = bias[e*NDIM + col];
            float bv1 = bias[e*NDIM + col + 1];
            int r0 = m0 + wm*64 + mi*16 + g;
            int r1 = r0 + 8;
            if(LAYER == 1){
                __half2 v0 = __floats2half2_rn(fmaxf(acc[mi][ni][0]+bv0, 0.f),
                                               fmaxf(acc[mi][ni][1]+bv1, 0.f));
                __half2 v1 = __floats2half2_rn(fmaxf(acc[mi][ni][2]+bv0, 0.f),
                                               fmaxf(acc[mi][ni][3]+bv1, 0.f));
                *reinterpret_cast<__half2*>(&g_hbuf[(size_t)(e*CAP + r0)*HID + col]) = v0;
                *reinterpret_cast<__half2*>(&g_hbuf[(size_t)(e*CAP + r1)*HID + col]) = v1;
            }else{
                float2 v0 = make_float2(acc[mi][ni][0]+bv0, acc[mi][ni][1]+bv1);
                float2 v1 = make_float2(acc[mi][ni][2]+bv0, acc[mi][ni][3]+bv1);
                *reinterpret_cast<float2*>(&g_outs[(size_t)(e*CAP + r0)*DIM + col]) = v0;
                *reinterpret_cast<float2*>(&g_outs[(size_t)(e*CAP + r1)*DIM + col]) = v1;
            }
        }
    }
}

// ---------------- combine: final[n] = sum_k w_k * outs[slot_k] ----------------
__global__ void __launch_bounds__(256) combine_kernel(float* __restrict__ out){
    const int n = blockIdx.x;
    const int tid = threadIdx.x;
    int s0 = g_slot[2*n], s1 = g_slot[2*n+1];
    float w0 = g_tw[2*n], w1 = g_tw[2*n+1];
    if(s0 < 0){ w0 = 0.f; s0 = 0; }
    if(s1 < 0){ w1 = 0.f; s1 = 0; }
    const float4* r0 = reinterpret_cast<const float4*>(g_outs + (size_t)s0*DIM);
    const float4* r1 = reinterpret_cast<const float4*>(g_outs + (size_t)s1*DIM);
    float4 a = r0[tid];
    float4 b = r1[tid];
    float4 v;
    v.x = w0*a.x + w1*b.x;
    v.y = w0*a.y + w1*b.y;
    v.z = w0*a.z + w1*b.z;
    v.w = w0*a.w + w1*b.w;
    reinterpret_cast<float4*>(out + (size_t)n*DIM)[tid] = v;
}

// ---------------- aux loss ----------------
__global__ void aux_kernel(float* __restrict__ out, int out_size){
    __shared__ float ps[NEXP];
    const int tid = threadIdx.x;
    if(tid < NEXP){
        float s = 0.f;
        for(int b = 0; b < RBLK; b++) s += g_pspart[b*NEXP + tid];
        ps[tid] = s;
    }
    __syncthreads();
    if(tid == 0){
        float bal = 0.f, imp = 0.f;
        for(int e = 0; e < NEXP; e++){
            float density = ps[e] / (float)N_TOK;
            float usage   = (float)g_counts[e] / (float)N_TOK;
            bal += density * usage;
            imp += ps[e] * ps[e];
        }
        float aux = bal * (float)NEXP + imp / (float)NEXP;
        if(out_size > N_TOK*DIM) out[(size_t)N_TOK*DIM] = aux;
    }
}

// ---------------- launch ----------------
extern "C" void kernel_launch(void* const* d_in, const int* in_sizes, int n_in,
                              void* d_out, int out_size){
    const float* x  = (const float*)d_in[0];
    const float* Wr = (const float*)d_in[1];
    const float* br = (const float*)d_in[2];
    const float* W1 = (const float*)d_in[3];
    const float* b1 = (const float*)d_in[4];
    const float* W2 = (const float*)d_in[5];
    const float* b2 = (const float*)d_in[6];
    float* out = (float*)d_out;

    init_kernel<<<1, 32>>>();
    router_kernel<<<RBLK, 256>>>(x, Wr, br);
    scan_kernel<<<NEXP, 256>>>();
    convert_kernel<<<4096, 256>>>((const float4*)W1, 0);
    convert_kernel<<<4096, 256>>>((const float4*)W2, 1);
    gemm_kernel<1><<<dim3(HID/128, CAP/128, NEXP), 256>>>(x, b1);
    gemm_kernel<2><<<dim3(DIM/128, CAP/128, NEXP), 256>>>(x, b2);
    combine_kernel<<<N_TOK, 256>>>(out);
    aux_kernel<<<1, 32>>>(out, out_size);
}

// round 3
// speedup vs baseline: 1.4371x; 1.4371x over previous
#include <cuda_runtime.h>
#include <cuda_fp16.h>
#include <cstdint>

#define N_TOK 16384
#define DIM   1024
#define HID   4096
#define NEXP  8
#define CAP   8192
#define RBLK  64

// ---------------- scratch (static device globals; no allocation) ----------------
__device__ __half g_W1h[(size_t)NEXP*DIM*HID];   // [e][D][H] fp16 = [e][K][N], 64 MB
__device__ __half g_W2h[(size_t)NEXP*HID*DIM];   // [e][H][D] fp16 = [e][K][N], 64 MB
__device__ __half g_xg [(size_t)NEXP*CAP*DIM];   // gathered x fp16, 128 MB
__device__ __half g_hbuf[(size_t)NEXP*CAP*HID];  // hidden fp16, 512 MB
__device__ float  g_outs[(size_t)NEXP*CAP*DIM];  // per-slot outputs fp32, 256 MB
__device__ int    g_sel[NEXP*CAP];
__device__ int    g_slot[N_TOK*2];
__device__ float  g_tw[N_TOK*2];
__device__ int    g_ti[N_TOK*2];
__device__ float  g_pspart[RBLK*NEXP];
__device__ int    g_counts[NEXP];
__device__ int    g_cnt[NEXP];

// ---------------- ptx helpers ----------------
__device__ __forceinline__ void cp16(uint32_t dst, const void* src){
    asm volatile("cp.async.cg.shared.global [%0], [%1], 16;" :: "r"(dst), "l"(src) : "memory");
}
__device__ __forceinline__ void cp_commit(){ asm volatile("cp.async.commit_group;" ::: "memory"); }
template<int N> __device__ __forceinline__ void cp_wait(){ asm volatile("cp.async.wait_group %0;" :: "n"(N) : "memory"); }

__device__ __forceinline__ void ldmA4(uint32_t a[4], uint32_t addr){
    asm volatile("ldmatrix.sync.aligned.m8n8.x4.shared.b16 {%0,%1,%2,%3}, [%4];"
        : "=r"(a[0]), "=r"(a[1]), "=r"(a[2]), "=r"(a[3]) : "r"(addr));
}
__device__ __forceinline__ void ldmB2(uint32_t b[2], uint32_t addr){
    asm volatile("ldmatrix.sync.aligned.m8n8.x2.trans.shared.b16 {%0,%1}, [%2];"
        : "=r"(b[0]), "=r"(b[1]) : "r"(addr));
}
__device__ __forceinline__ void mma16816(float c[4], const uint32_t a[4], const uint32_t b[2]){
    asm volatile("mma.sync.aligned.m16n8k16.row.col.f32.f16.f16.f32 "
        "{%0,%1,%2,%3}, {%4,%5,%6,%7}, {%8,%9}, {%0,%1,%2,%3};"
        : "+f"(c[0]), "+f"(c[1]), "+f"(c[2]), "+f"(c[3])
        : "r"(a[0]), "r"(a[1]), "r"(a[2]), "r"(a[3]), "r"(b[0]), "r"(b[1]));
}

// ---------------- init ----------------
__global__ void init_kernel(){
    if(threadIdx.x < NEXP) g_counts[threadIdx.x] = 0;
}

// ---------------- router ----------------
__global__ void __launch_bounds__(256) router_kernel(const float* __restrict__ x,
                                                     const float* __restrict__ Wr,
                                                     const float* __restrict__ br){
    __shared__ float sW[DIM*NEXP];
    __shared__ float sPS[NEXP];
    const int tid = threadIdx.x;
    for(int i = tid; i < DIM*NEXP; i += 256) sW[i] = Wr[i];
    if(tid < NEXP) sPS[tid] = 0.f;
    __syncthreads();

    const int n = blockIdx.x*256 + tid;
    float acc[NEXP];
    #pragma unroll
    for(int e=0;e<NEXP;e++) acc[e] = br[e];
    const float4* xr = reinterpret_cast<const float4*>(x + (size_t)n*DIM);
    for(int d4 = 0; d4 < DIM/4; d4++){
        float4 v = xr[d4];
        const float* w = &sW[d4*4*NEXP];
        #pragma unroll
        for(int e=0;e<NEXP;e++)
            acc[e] += v.x*w[e] + v.y*w[NEXP+e] + v.z*w[2*NEXP+e] + v.w*w[3*NEXP+e];
    }
    float m = acc[0];
    #pragma unroll
    for(int e=1;e<NEXP;e++) m = fmaxf(m, acc[e]);
    float p[NEXP]; float s = 0.f;
    #pragma unroll
    for(int e=0;e<NEXP;e++){ p[e] = expf(acc[e]-m); s += p[e]; }
    float inv = 1.f/s;
    #pragma unroll
    for(int e=0;e<NEXP;e++) p[e] *= inv;

    int i0 = 0;
    #pragma unroll
    for(int e=1;e<NEXP;e++) if(p[e] > p[i0]) i0 = e;
    int i1 = -1;
    #pragma unroll
    for(int e=0;e<NEXP;e++) if(e != i0 && (i1 < 0 || p[e] > p[i1])) i1 = e;

    g_ti[2*n]   = i0;  g_ti[2*n+1]   = i1;
    g_tw[2*n]   = p[i0]; g_tw[2*n+1] = p[i1];
    g_slot[2*n] = -1;  g_slot[2*n+1] = -1;
    atomicAdd(&g_counts[i0], 1);
    atomicAdd(&g_counts[i1], 1);

    #pragma unroll
    for(int e=0;e<NEXP;e++){
        float v = p[e];
        for(int off=16; off; off >>= 1) v += __shfl_down_sync(0xffffffffu, v, off);
        if((tid & 31) == 0) atomicAdd(&sPS[e], v);
    }
    __syncthreads();
    if(tid < NEXP) g_pspart[blockIdx.x*NEXP + tid] = sPS[tid];
}

// ---------------- per-expert capacity scan ----------------
__global__ void __launch_bounds__(256) scan_kernel(){
    const int e = blockIdx.x;
    const int tid = threadIdx.x;
    __shared__ int sS[256];
    int base = 0;
    for(int c = 0; c < N_TOK/256; c++){
        int n = c*256 + tid;
        int i0 = g_ti[2*n], i1 = g_ti[2*n+1];
        int kk = (i0 == e) ? 0 : ((i1 == e) ? 1 : -1);
        int flag = (kk >= 0) ? 1 : 0;
        sS[tid] = flag; __syncthreads();
        for(int off = 1; off < 256; off <<= 1){
            int v = (tid >= off) ? sS[tid-off] : 0;
            __syncthreads();
            sS[tid] += v; __syncthreads();
        }
        int pos = base + sS[tid] - flag;
        if(flag && pos < CAP){
            g_sel[e*CAP + pos] = n;
            g_slot[2*n + kk] = e*CAP + pos;
        }
        base += sS[255];
        __syncthreads();
    }
    int cnt = min(base, CAP);
    if(tid == 0) g_cnt[e] = cnt;
    for(int i = cnt + tid; i < CAP; i += 256) g_sel[e*CAP + i] = 0;
}

// ---------------- gather x rows -> fp16 (round up to 256-row tiles) ----------------
__global__ void __launch_bounds__(256) gather_kernel(const float* __restrict__ x){
    const int e = blockIdx.y;
    const int i = blockIdx.x;
    const int rup = (g_cnt[e] + 255) & ~255;
    if(i >= rup) return;
    const int src = g_sel[e*CAP + i];
    const float4* s = reinterpret_cast<const float4*>(x + (size_t)src*DIM);
    __half2* d = reinterpret_cast<__half2*>(g_xg + ((size_t)e*CAP + i)*DIM);
    const int t = threadIdx.x;
    float4 v = s[t];
    d[2*t]   = __floats2half2_rn(v.x, v.y);
    d[2*t+1] = __floats2half2_rn(v.z, v.w);
}

// ---------------- fp32 -> fp16 weight conversion (layout-preserving) ----------------
__global__ void __launch_bounds__(256) convert_kernel(const float4* __restrict__ src, int which){
    __half2* dst = reinterpret_cast<__half2*>(which == 0 ? g_W1h : g_W2h);
    const int n4 = NEXP*DIM*HID/4;
    for(int i = blockIdx.x*blockDim.x + threadIdx.x; i < n4; i += gridDim.x*blockDim.x){
        float4 v = src[i];
        dst[2*i]   = __floats2half2_rn(v.x, v.y);
        dst[2*i+1] = __floats2half2_rn(v.z, v.w);
    }
}

// ---------------- HMMA grouped GEMM, cp.async 4-stage pipeline ----------------
// BM=256, BN=128, BK=32. 256 threads = 8 warps, warp tile 64x64 (wm 0..3, wn 0..1).
// A fp16 [rows][KDIM] (g_xg / g_hbuf), B fp16 [KDIM][NDIM] (weights natural layout).
template<int KDIM, int NDIM, int LAYER>
__global__ void __launch_bounds__(256,1) gemm_hmma(const float* __restrict__ bias){
    constexpr int BM = 256, BN = 128, BK = 32, STAGES = 4;
    constexpr int KT = KDIM / BK;
    constexpr int ASTR = BK + 8;                 // 40 halves
    constexpr int BSTR = BN + 8;                 // 136 halves
    constexpr int ABYTES = BM*ASTR*2;            // 20480
    constexpr int BBYTES = BK*BSTR*2;            // 8704
    constexpr int SBYTES = ABYTES + BBYTES;      // 29184

    const int e  = blockIdx.z;
    const int m0 = blockIdx.y * BM;
    const int n0 = blockIdx.x * BN;
    if(m0 >= g_cnt[e]) return;

    extern __shared__ char smem[];
    const uint32_t base = (uint32_t)__cvta_generic_to_shared(smem);

    const int tid  = threadIdx.x;
    const int wid  = tid >> 5, lane = tid & 31;
    const int wm   = wid & 3, wn = wid >> 2;
    const int lrow = lane & 15, lcol8 = (lane >> 4) * 8;

    const __half* __restrict__ Aexp =
        ((LAYER == 1) ? g_xg : g_hbuf) + ((size_t)e*CAP + m0)*KDIM;
    const __half* __restrict__ Bexp =
        ((LAYER == 1) ? g_W1h : g_W2h) + (size_t)e*KDIM*NDIM + n0;

    auto loadStage = [&](int s, int kb){
        const uint32_t sa = base + s*SBYTES;
        // A: 256 rows x 32 halves = 1024 16B-chunks
        #pragma unroll
        for(int p=0;p<4;p++){
            int idx = tid + p*256;
            int r = idx >> 2, c = (idx & 3) * 8;
            cp16(sa + (r*ASTR + c)*2, Aexp + (size_t)r*KDIM + kb*BK + c);
        }
        // B: 32 rows x 128 halves = 512 16B-chunks
        #pragma unroll
        for(int p=0;p<2;p++){
            int idx = tid + p*256;
            int r = idx >> 4, c = (idx & 15) * 8;
            cp16(sa + ABYTES + (r*BSTR + c)*2, Bexp + (size_t)(kb*BK + r)*NDIM + c);
        }
    };

    float acc[4][8][4];
    #pragma unroll
    for(int mi=0;mi<4;mi++)
        #pragma unroll
        for(int ni=0;ni<8;ni++)
            #pragma unroll
            for(int q=0;q<4;q++) acc[mi][ni][q] = 0.f;

    // prefetch STAGES-1 stages
    #pragma unroll
    for(int s=0;s<STAGES-1;s++){ loadStage(s, s); cp_commit(); }

    for(int kt = 0; kt < KT; kt++){
        cp_wait<STAGES-2>();
        __syncthreads();
        if(kt + STAGES-1 < KT) loadStage((kt + STAGES-1) & (STAGES-1), kt + STAGES-1);
        cp_commit();

        const uint32_t sa = base + (kt & (STAGES-1))*SBYTES;
        #pragma unroll
        for(int ks=0;ks<2;ks++){
            uint32_t a[4][4], b[8][2];
            #pragma unroll
            for(int mi=0;mi<4;mi++)
                ldmA4(a[mi], sa + ((wm*64 + mi*16 + lrow)*ASTR + ks*16 + lcol8)*2);
            #pragma unroll
            for(int ni=0;ni<8;ni++)
                ldmB2(b[ni], sa + ABYTES + ((ks*16 + lrow)*BSTR + wn*64 + ni*8)*2);
            #pragma unroll
            for(int mi=0;mi<4;mi++)
                #pragma unroll
                for(int ni=0;ni<8;ni++)
                    mma16816(acc[mi][ni], a[mi], b[ni]);
        }
    }

    // epilogue
    const int g = lane >> 2;
    const int t = lane & 3;
    #pragma unroll
    for(int mi=0;mi<4;mi++){
        #pragma unroll
        for(int ni=0;ni<8;ni++){
            int col = n0 + wn*64 + ni*8 + t*2;
            float bv0 = __ldg(&bias[e*NDIM + col]);
            float bv1 = __ldg(&bias[e*NDIM + col + 1]);
            int r0 = m0 + wm*64 + mi*16 + g;
            int r1 = r0 + 8;
            if(LAYER == 1){
                __half2 v0 = __floats2half2_rn(fmaxf(acc[mi][ni][0]+bv0, 0.f),
                                               fmaxf(acc[mi][ni][1]+bv1, 0.f));
                __half2 v1 = __floats2half2_rn(fmaxf(acc[mi][ni][2]+bv0, 0.f),
                                               fmaxf(acc[mi][ni][3]+bv1, 0.f));
                *reinterpret_cast<__half2*>(&g_hbuf[((size_t)e*CAP + r0)*HID + col]) = v0;
                *reinterpret_cast<__half2*>(&g_hbuf[((size_t)e*CAP + r1)*HID + col]) = v1;
            }else{
                float2 v0 = make_float2(acc[mi][ni][0]+bv0, acc[mi][ni][1]+bv1);
                float2 v1 = make_float2(acc[mi][ni][2]+bv0, acc[mi][ni][3]+bv1);
                *reinterpret_cast<float2*>(&g_outs[((size_t)e*CAP + r0)*DIM + col]) = v0;
                *reinterpret_cast<float2*>(&g_outs[((size_t)e*CAP + r1)*DIM + col]) = v1;
            }
        }
    }
}

// ---------------- combine ----------------
__global__ void __launch_bounds__(256) combine_kernel(float* __restrict__ out){
    const int n = blockIdx.x;
    const int tid = threadIdx.x;
    int s0 = g_slot[2*n], s1 = g_slot[2*n+1];
    float w0 = g_tw[2*n], w1 = g_tw[2*n+1];
    if(s0 < 0){ w0 = 0.f; s0 = 0; }
    if(s1 < 0){ w1 = 0.f; s1 = 0; }
    const float4* r0 = reinterpret_cast<const float4*>(g_outs + (size_t)s0*DIM);
    const float4* r1 = reinterpret_cast<const float4*>(g_outs + (size_t)s1*DIM);
    float4 a = r0[tid];
    float4 b = r1[tid];
    float4 v;
    v.x = w0*a.x + w1*b.x;
    v.y = w0*a.y + w1*b.y;
    v.z = w0*a.z + w1*b.z;
    v.w = w0*a.w + w1*b.w;
    reinterpret_cast<float4*>(out + (size_t)n*DIM)[tid] = v;
}

// ---------------- aux loss ----------------
__global__ void aux_kernel(float* __restrict__ out, int out_size){
    __shared__ float ps[NEXP];
    const int tid = threadIdx.x;
    if(tid < NEXP){
        float s = 0.f;
        for(int b = 0; b < RBLK; b++) s += g_pspart[b*NEXP + tid];
        ps[tid] = s;
    }
    __syncthreads();
    if(tid == 0){
        float bal = 0.f, imp = 0.f;
        for(int e = 0; e < NEXP; e++){
            float density = ps[e] / (float)N_TOK;
            float usage   = (float)g_counts[e] / (float)N_TOK;
            bal += density * usage;
            imp += ps[e] * ps[e];
        }
        float aux = bal * (float)NEXP + imp / (float)NEXP;
        if(out_size > N_TOK*DIM) out[(size_t)N_TOK*DIM] = aux;
    }
}

// ---------------- launch ----------------
extern "C" void kernel_launch(void* const* d_in, const int* in_sizes, int n_in,
                              void* d_out, int out_size){
    const float* x  = (const float*)d_in[0];
    const float* Wr = (const float*)d_in[1];
    const float* br = (const float*)d_in[2];
    const float* W1 = (const float*)d_in[3];
    const float* b1 = (const float*)d_in[4];
    const float* W2 = (const float*)d_in[5];
    const float* b2 = (const float*)d_in[6];
    float* out = (float*)d_out;

    const int SMEM_BYTES = 4 * (256*40*2 + 32*136*2);  // 116736
    cudaFuncSetAttribute(gemm_hmma<DIM, HID, 1>, cudaFuncAttributeMaxDynamicSharedMemorySize, SMEM_BYTES);
    cudaFuncSetAttribute(gemm_hmma<HID, DIM, 2>, cudaFuncAttributeMaxDynamicSharedMemorySize, SMEM_BYTES);

    init_kernel<<<1, 32>>>();
    router_kernel<<<RBLK, 256>>>(x, Wr, br);
    scan_kernel<<<NEXP, 256>>>();
    gather_kernel<<<dim3(CAP, NEXP), 256>>>(x);
    convert_kernel<<<4096, 256>>>((const float4*)W1, 0);
    convert_kernel<<<4096, 256>>>((const float4*)W2, 1);
    gemm_hmma<DIM, HID, 1><<<dim3(HID/128, CAP/256, NEXP), 256, SMEM_BYTES>>>(b1);
    gemm_hmma<HID, DIM, 2><<<dim3(DIM/128, CAP/256, NEXP), 256, SMEM_BYTES>>>(b2);
    combine_kernel<<<N_TOK, 256>>>(out);
    aux_kernel<<<1, 32>>>(out, out_size);
}

// round 7
// speedup vs baseline: 1.4896x; 1.0366x over previous
#include <cuda_runtime.h>
#include <cuda_fp16.h>
#include <cstdint>

#define N_TOK 16384
#define DIM   1024
#define HID   4096
#define NEXP  8
#define CAP   8192
#define RBLK  64

// ---------------- scratch (static device globals; no allocation) ----------------
__device__ __half g_W1h[(size_t)NEXP*DIM*HID];   // [e][D][H] fp16 = [e][K][N], 64 MB
__device__ __half g_W2h[(size_t)NEXP*HID*DIM];   // [e][H][D] fp16 = [e][K][N], 64 MB
__device__ __half g_xg [(size_t)NEXP*CAP*DIM];   // gathered x fp16, 128 MB
__device__ __half g_hbuf[(size_t)NEXP*CAP*HID];  // hidden fp16, 512 MB
__device__ float  g_outs[(size_t)NEXP*CAP*DIM];  // per-slot outputs fp32, 256 MB
__device__ int    g_sel[NEXP*CAP];
__device__ int    g_slot[N_TOK*2];
__device__ float  g_tw[N_TOK*2];
__device__ int    g_ti[N_TOK*2];
__device__ float  g_pspart[RBLK*NEXP];
__device__ int    g_counts[NEXP];   // uncapped mask counts (for aux)
__device__ int    g_cnt[NEXP];      // capped counts (for GEMM sizing)

// ---------------- ptx helpers ----------------
__device__ __forceinline__ void cp16(uint32_t dst, const void* src){
    asm volatile("cp.async.cg.shared.global [%0], [%1], 16;" :: "r"(dst), "l"(src) : "memory");
}
__device__ __forceinline__ void cp_commit(){ asm volatile("cp.async.commit_group;" ::: "memory"); }
template<int N> __device__ __forceinline__ void cp_wait(){ asm volatile("cp.async.wait_group %0;" :: "n"(N) : "memory"); }

__device__ __forceinline__ void ldmA4(uint32_t a[4], uint32_t addr){
    asm volatile("ldmatrix.sync.aligned.m8n8.x4.shared.b16 {%0,%1,%2,%3}, [%4];"
        : "=r"(a[0]), "=r"(a[1]), "=r"(a[2]), "=r"(a[3]) : "r"(addr));
}
__device__ __forceinline__ void ldmB4t(uint32_t b[4], uint32_t addr){
    asm volatile("ldmatrix.sync.aligned.m8n8.x4.trans.shared.b16 {%0,%1,%2,%3}, [%4];"
        : "=r"(b[0]), "=r"(b[1]), "=r"(b[2]), "=r"(b[3]) : "r"(addr));
}
__device__ __forceinline__ void mma16816(float c[4], const uint32_t a[4], const uint32_t b0, const uint32_t b1){
    asm volatile("mma.sync.aligned.m16n8k16.row.col.f32.f16.f16.f32 "
        "{%0,%1,%2,%3}, {%4,%5,%6,%7}, {%8,%9}, {%0,%1,%2,%3};"
        : "+f"(c[0]), "+f"(c[1]), "+f"(c[2]), "+f"(c[3])
        : "r"(a[0]), "r"(a[1]), "r"(a[2]), "r"(a[3]), "r"(b0), "r"(b1));
}

// ---------------- router ----------------
__global__ void __launch_bounds__(256) router_kernel(const float* __restrict__ x,
                                                     const float* __restrict__ Wr,
                                                     const float* __restrict__ br){
    __shared__ float sW[DIM*NEXP];
    __shared__ float sPS[NEXP];
    const int tid = threadIdx.x;
    for(int i = tid; i < DIM*NEXP; i += 256) sW[i] = Wr[i];
    if(tid < NEXP) sPS[tid] = 0.f;
    __syncthreads();

    const int n = blockIdx.x*256 + tid;
    float acc[NEXP];
    #pragma unroll
    for(int e=0;e<NEXP;e++) acc[e] = br[e];
    const float4* xr = reinterpret_cast<const float4*>(x + (size_t)n*DIM);
    for(int d4 = 0; d4 < DIM/4; d4++){
        float4 v = xr[d4];
        const float* w = &sW[d4*4*NEXP];
        #pragma unroll
        for(int e=0;e<NEXP;e++)
            acc[e] += v.x*w[e] + v.y*w[NEXP+e] + v.z*w[2*NEXP+e] + v.w*w[3*NEXP+e];
    }
    float m = acc[0];
    #pragma unroll
    for(int e=1;e<NEXP;e++) m = fmaxf(m, acc[e]);
    float p[NEXP]; float s = 0.f;
    #pragma unroll
    for(int e=0;e<NEXP;e++){ p[e] = expf(acc[e]-m); s += p[e]; }
    float inv = 1.f/s;
    #pragma unroll
    for(int e=0;e<NEXP;e++) p[e] *= inv;

    int i0 = 0;
    #pragma unroll
    for(int e=1;e<NEXP;e++) if(p[e] > p[i0]) i0 = e;
    int i1 = -1;
    #pragma unroll
    for(int e=0;e<NEXP;e++) if(e != i0 && (i1 < 0 || p[e] > p[i1])) i1 = e;

    g_ti[2*n]   = i0;  g_ti[2*n+1]   = i1;
    g_tw[2*n]   = p[i0]; g_tw[2*n+1] = p[i1];
    g_slot[2*n] = -1;  g_slot[2*n+1] = -1;

    #pragma unroll
    for(int e=0;e<NEXP;e++){
        float v = p[e];
        for(int off=16; off; off >>= 1) v += __shfl_down_sync(0xffffffffu, v, off);
        if((tid & 31) == 0) atomicAdd(&sPS[e], v);
    }
    __syncthreads();
    if(tid < NEXP) g_pspart[blockIdx.x*NEXP + tid] = sPS[tid];
}

// ---------------- per-expert capacity scan (ballot-based) ----------------
__global__ void __launch_bounds__(256) scan_kernel(){
    const int e = blockIdx.x;
    const int tid = threadIdx.x;
    const int lane = tid & 31, w = tid >> 5;
    __shared__ int wsum[8];
    int base = 0;
    for(int c = 0; c < N_TOK/256; c++){
        int n = c*256 + tid;
        int i0 = g_ti[2*n], i1 = g_ti[2*n+1];
        int kk = (i0 == e) ? 0 : ((i1 == e) ? 1 : -1);
        int flag = (kk >= 0) ? 1 : 0;
        unsigned bal = __ballot_sync(0xffffffffu, flag);
        int pre = __popc(bal & ((1u << lane) - 1u));
        if(lane == 0) wsum[w] = __popc(bal);
        __syncthreads();
        int woff = 0, ctot = 0;
        #pragma unroll
        for(int q=0;q<8;q++){
            int v = wsum[q];
            if(q < w) woff += v;
            ctot += v;
        }
        int pos = base + woff + pre;
        if(flag && pos < CAP){
            g_sel[e*CAP + pos] = n;
            g_slot[2*n + kk] = e*CAP + pos;
        }
        base += ctot;
        __syncthreads();
    }
    int cnt = min(base, CAP);
    if(tid == 0){ g_cnt[e] = cnt; g_counts[e] = base; }
    for(int i = cnt + tid; i < CAP; i += 256) g_sel[e*CAP + i] = 0;
}

// ---------------- prep: gather x -> fp16 + convert W1,W2 -> fp16 (fused) ----------------
// blocks [0, 8192): gather, 8 rows each
// blocks [8192, 16384): convert W1 (4 float4 per thread)
// blocks [16384, 24576): convert W2
__global__ void __launch_bounds__(256) prep_kernel(const float* __restrict__ x,
                                                   const float4* __restrict__ W1,
                                                   const float4* __restrict__ W2){
    const int b = blockIdx.x;
    const int tid = threadIdx.x;
    if(b < 8192){
        const int e  = b >> 10;            // 1024 blocks per expert
        const int rg = b & 1023;           // row group (8 rows)
        const int rup = (g_cnt[e] + 255) & ~255;
        if(rg*8 >= rup) return;
        #pragma unroll
        for(int i=0;i<8;i++){
            int flat = tid + i*256;        // 2048 float4 chunks
            int r  = rg*8 + (flat >> 8);
            int c4 = flat & 255;
            const int src = g_sel[e*CAP + r];
            float4 v = reinterpret_cast<const float4*>(x + (size_t)src*DIM)[c4];
            __half2* d = reinterpret_cast<__half2*>(g_xg + ((size_t)e*CAP + r)*DIM) + 2*c4;
            d[0] = __floats2half2_rn(v.x, v.y);
            d[1] = __floats2half2_rn(v.z, v.w);
        }
    }else{
        const int which = (b < 16384) ? 0 : 1;
        const int b2 = b - (which ? 16384 : 8192);
        const float4* src = which ? W2 : W1;
        __half2* dst = reinterpret_cast<__half2*>(which ? g_W2h : g_W1h);
        const int i0 = b2*256 + tid;
        #pragma unroll
        for(int j=0;j<4;j++){
            int i = i0 + j*(8192*256);
            float4 v = src[i];
            dst[2*i]   = __floats2half2_rn(v.x, v.y);
            dst[2*i+1] = __floats2half2_rn(v.z, v.w);
        }
    }
}

// ---------------- HMMA grouped GEMM, cp.async 4-stage pipeline ----------------
// BM=256, BN=128, BK=32. 8 warps, warp tile 64x64 (wm 0..3, wn 0..1).
template<int KDIM, int NDIM, int LAYER>
__global__ void __launch_bounds__(256,1) gemm_hmma(const float* __restrict__ bias){
    constexpr int BM = 256, BN = 128, BK = 32, STAGES = 4;
    constexpr int KT = KDIM / BK;
    constexpr int ASTR = BK + 8;                 // 40 halves
    constexpr int BSTR = BN + 8;                 // 136 halves
    constexpr int ABYTES = BM*ASTR*2;            // 20480
    constexpr int BBYTES = BK*BSTR*2;            // 8704
    constexpr int SBYTES = ABYTES + BBYTES;      // 29184

    const int e  = blockIdx.z;
    const int m0 = blockIdx.y * BM;
    const int n0 = blockIdx.x * BN;
    if(m0 >= g_cnt[e]) return;

    extern __shared__ char smem[];
    const uint32_t base = (uint32_t)__cvta_generic_to_shared(smem);

    const int tid  = threadIdx.x;
    const int wid  = tid >> 5, lane = tid & 31;
    const int wm   = wid & 3, wn = wid >> 2;
    const int lrow = lane & 15, lcol8 = (lane >> 4) * 8;
    // ldmB4t addressing: quad = lane>>3 (0..3), j = lane&7
    const int bq = lane >> 3, bj = lane & 7;
    const int brow = (bq & 1)*8 + bj;            // k within 16
    const int bcol = (bq >> 1)*8;                // n within 16

    const __half* __restrict__ Aexp =
        ((LAYER == 1) ? g_xg : g_hbuf) + ((size_t)e*CAP + m0)*KDIM;
    const __half* __restrict__ Bexp =
        ((LAYER == 1) ? g_W1h : g_W2h) + (size_t)e*KDIM*NDIM + n0;

    auto loadStage = [&](int s, int kb){
        const uint32_t sa = base + s*SBYTES;
        #pragma unroll
        for(int p=0;p<4;p++){
            int idx = tid + p*256;
            int r = idx >> 2, c = (idx & 3) * 8;
            cp16(sa + (r*ASTR + c)*2, Aexp + (size_t)r*KDIM + kb*BK + c);
        }
        #pragma unroll
        for(int p=0;p<2;p++){
            int idx = tid + p*256;
            int r = idx >> 4, c = (idx & 15) * 8;
            cp16(sa + ABYTES + (r*BSTR + c)*2, Bexp + (size_t)(kb*BK + r)*NDIM + c);
        }
    };

    float acc[4][8][4];
    #pragma unroll
    for(int mi=0;mi<4;mi++)
        #pragma unroll
        for(int ni=0;ni<8;ni++)
            #pragma unroll
            for(int q=0;q<4;q++) acc[mi][ni][q] = 0.f;

    #pragma unroll
    for(int s=0;s<STAGES-1;s++){ loadStage(s, s); cp_commit(); }

    for(int kt = 0; kt < KT; kt++){
        cp_wait<STAGES-2>();
        __syncthreads();
        if(kt + STAGES-1 < KT) loadStage((kt + STAGES-1) & (STAGES-1), kt + STAGES-1);
        cp_commit();

        const uint32_t sa = base + (kt & (STAGES-1))*SBYTES;
        #pragma unroll
        for(int ks=0;ks<2;ks++){
            uint32_t a[4][4], b[4][4];
            #pragma unroll
            for(int mi=0;mi<4;mi++)
                ldmA4(a[mi], sa + ((wm*64 + mi*16 + lrow)*ASTR + ks*16 + lcol8)*2);
            #pragma unroll
            for(int np=0;np<4;np++)
                ldmB4t(b[np], sa + ABYTES + ((ks*16 + brow)*BSTR + wn*64 + np*16 + bcol)*2);
            #pragma unroll
            for(int mi=0;mi<4;mi++)
                #pragma unroll
                for(int np=0;np<4;np++){
                    mma16816(acc[mi][2*np],   a[mi], b[np][0], b[np][1]);
                    mma16816(acc[mi][2*np+1], a[mi], b[np][2], b[np][3]);
                }
        }
    }

    // epilogue
    const int g = lane >> 2;
    const int t = lane & 3;
    #pragma unroll
    for(int mi=0;mi<4;mi++){
        #pragma unroll
        for(int ni=0;ni<8;ni++){
            int col = n0 + wn*64 + ni*8 + t*2;
            float bv0 = __ldg(&bias[e*NDIM + col]);
            float bv1 = __ldg(&bias[e*NDIM + col + 1]);
            int r0 = m0 + wm*64 + mi*16 + g;
            int r1 = r0 + 8;
            if(LAYER == 1){
                __half2 v0 = __floats2half2_rn(fmaxf(acc[mi][ni][0]+bv0, 0.f),
                                               fmaxf(acc[mi][ni][1]+bv1, 0.f));
                __half2 v1 = __floats2half2_rn(fmaxf(acc[mi][ni][2]+bv0, 0.f),
                                               fmaxf(acc[mi][ni][3]+bv1, 0.f));
                *reinterpret_cast<__half2*>(&g_hbuf[((size_t)e*CAP + r0)*HID + col]) = v0;
                *reinterpret_cast<__half2*>(&g_hbuf[((size_t)e*CAP + r1)*HID + col]) = v1;
            }else{
                float2 v0 = make_float2(acc[mi][ni][0]+bv0, acc[mi][ni][1]+bv1);
                float2 v1 = make_float2(acc[mi][ni][2]+bv0, acc[mi][ni][3]+bv1);
                *reinterpret_cast<float2*>(&g_outs[((size_t)e*CAP + r0)*DIM + col]) = v0;
                *reinterpret_cast<float2*>(&g_outs[((size_t)e*CAP + r1)*DIM + col]) = v1;
            }
        }
    }
}

// ---------------- combine ----------------
__global__ void __launch_bounds__(256) combine_kernel(float* __restrict__ out){
    const int n = blockIdx.x;
    const int tid = threadIdx.x;
    int s0 = g_slot[2*n], s1 = g_slot[2*n+1];
    float w0 = g_tw[2*n], w1 = g_tw[2*n+1];
    if(s0 < 0){ w0 = 0.f; s0 = 0; }
    if(s1 < 0){ w1 = 0.f; s1 = 0; }
    const float4* r0 = reinterpret_cast<const float4*>(g_outs + (size_t)s0*DIM);
    const float4* r1 = reinterpret_cast<const float4*>(g_outs + (size_t)s1*DIM);
    float4 a = r0[tid];
    float4 b = r1[tid];
    float4 v;
    v.x = w0*a.x + w1*b.x;
    v.y = w0*a.y + w1*b.y;
    v.z = w0*a.z + w1*b.z;
    v.w = w0*a.w + w1*b.w;
    reinterpret_cast<float4*>(out + (size_t)n*DIM)[tid] = v;
}

// ---------------- aux loss ----------------
__global__ void aux_kernel(float* __restrict__ out, int out_size){
    __shared__ float ps[NEXP];
    const int tid = threadIdx.x;
    if(tid < NEXP){
        float s = 0.f;
        for(int b = 0; b < RBLK; b++) s += g_pspart[b*NEXP + tid];
        ps[tid] = s;
    }
    __syncthreads();
    if(tid == 0){
        float bal = 0.f, imp = 0.f;
        for(int e = 0; e < NEXP; e++){
            float density = ps[e] / (float)N_TOK;
            float usage   = (float)g_counts[e] / (float)N_TOK;
            bal += density * usage;
            imp += ps[e] * ps[e];
        }
        float aux = bal * (float)NEXP + imp / (float)NEXP;
        if(out_size > N_TOK*DIM) out[(size_t)N_TOK*DIM] = aux;
    }
}

// ---------------- launch ----------------
extern "C" void kernel_launch(void* const* d_in, const int* in_sizes, int n_in,
                              void* d_out, int out_size){
    const float* x  = (const float*)d_in[0];
    const float* Wr = (const float*)d_in[1];
    const float* br = (const float*)d_in[2];
    const float* W1 = (const float*)d_in[3];
    const float* b1 = (const float*)d_in[4];
    const float* W2 = (const float*)d_in[5];
    const float* b2 = (const float*)d_in[6];
    float* out = (float*)d_out;

    const int SMEM_BYTES = 4 * (256*40*2 + 32*136*2);  // 116736
    cudaFuncSetAttribute(gemm_hmma<DIM, HID, 1>, cudaFuncAttributeMaxDynamicSharedMemorySize, SMEM_BYTES);
    cudaFuncSetAttribute(gemm_hmma<HID, DIM, 2>, cudaFuncAttributeMaxDynamicSharedMemorySize, SMEM_BYTES);

    router_kernel<<<RBLK, 256>>>(x, Wr, br);
    scan_kernel<<<NEXP, 256>>>();
    prep_kernel<<<24576, 256>>>(x, (const float4*)W1, (const float4*)W2);
    gemm_hmma<DIM, HID, 1><<<dim3(HID/128, CAP/256, NEXP), 256, SMEM_BYTES>>>(b1);
    gemm_hmma<HID, DIM, 2><<<dim3(DIM/128, CAP/256, NEXP), 256, SMEM_BYTES>>>(b2);
    combine_kernel<<<N_TOK, 256>>>(out);
    aux_kernel<<<1, 32>>>(out, out_size);
}

// round 8
// speedup vs baseline: 1.5943x; 1.0703x over previous
#include <cuda_runtime.h>
#include <cuda_fp16.h>
#include <cstdint>

#define N_TOK 16384
#define DIM   1024
#define HID   4096
#define NEXP  8
#define CAP   8192
#define RBLK  64

// ---------------- scratch (static device globals; no allocation) ----------------
__device__ __half g_W1h[(size_t)NEXP*DIM*HID];   // [e][D][H] fp16 = [e][K][N], 64 MB
__device__ __half g_W2h[(size_t)NEXP*HID*DIM];   // [e][H][D] fp16 = [e][K][N], 64 MB
__device__ __half g_xg [(size_t)NEXP*CAP*DIM];   // gathered x fp16, 128 MB
__device__ __half g_hbuf[(size_t)NEXP*CAP*HID];  // hidden fp16, 512 MB
__device__ float  g_outs[(size_t)NEXP*CAP*DIM];  // per-slot outputs fp32, 256 MB
__device__ int    g_sel[NEXP*CAP];
__device__ int    g_slot[N_TOK*2];
__device__ float  g_tw[N_TOK*2];
__device__ int    g_ti[N_TOK*2];
__device__ float  g_pspart[RBLK*NEXP];
__device__ int    g_counts[NEXP];   // uncapped mask counts (for aux)
__device__ int    g_cnt[NEXP];      // capped counts (for GEMM sizing)

// ---------------- ptx helpers ----------------
__device__ __forceinline__ void cp16(uint32_t dst, const void* src){
    asm volatile("cp.async.cg.shared.global [%0], [%1], 16;" :: "r"(dst), "l"(src) : "memory");
}
__device__ __forceinline__ void cp_commit(){ asm volatile("cp.async.commit_group;" ::: "memory"); }
template<int N> __device__ __forceinline__ void cp_wait(){ asm volatile("cp.async.wait_group %0;" :: "n"(N) : "memory"); }

__device__ __forceinline__ void ldmA4(uint32_t a[4], uint32_t addr){
    asm volatile("ldmatrix.sync.aligned.m8n8.x4.shared.b16 {%0,%1,%2,%3}, [%4];"
        : "=r"(a[0]), "=r"(a[1]), "=r"(a[2]), "=r"(a[3]) : "r"(addr));
}
__device__ __forceinline__ void ldmB4t(uint32_t b[4], uint32_t addr){
    asm volatile("ldmatrix.sync.aligned.m8n8.x4.trans.shared.b16 {%0,%1,%2,%3}, [%4];"
        : "=r"(b[0]), "=r"(b[1]), "=r"(b[2]), "=r"(b[3]) : "r"(addr));
}
__device__ __forceinline__ void mma16816(float c[4], const uint32_t a[4], const uint32_t b0, const uint32_t b1){
    asm volatile("mma.sync.aligned.m16n8k16.row.col.f32.f16.f16.f32 "
        "{%0,%1,%2,%3}, {%4,%5,%6,%7}, {%8,%9}, {%0,%1,%2,%3};"
        : "+f"(c[0]), "+f"(c[1]), "+f"(c[2]), "+f"(c[3])
        : "r"(a[0]), "r"(a[1]), "r"(a[2]), "r"(a[3]), "r"(b0), "r"(b1));
}

// ---------------- router ----------------
__global__ void __launch_bounds__(256) router_kernel(const float* __restrict__ x,
                                                     const float* __restrict__ Wr,
                                                     const float* __restrict__ br){
    __shared__ float sW[DIM*NEXP];
    __shared__ float sPS[NEXP];
    const int tid = threadIdx.x;
    for(int i = tid; i < DIM*NEXP; i += 256) sW[i] = Wr[i];
    if(tid < NEXP) sPS[tid] = 0.f;
    __syncthreads();

    const int n = blockIdx.x*256 + tid;
    float acc[NEXP];
    #pragma unroll
    for(int e=0;e<NEXP;e++) acc[e] = br[e];
    const float4* xr = reinterpret_cast<const float4*>(x + (size_t)n*DIM);
    for(int d4 = 0; d4 < DIM/4; d4++){
        float4 v = xr[d4];
        const float* w = &sW[d4*4*NEXP];
        #pragma unroll
        for(int e=0;e<NEXP;e++)
            acc[e] += v.x*w[e] + v.y*w[NEXP+e] + v.z*w[2*NEXP+e] + v.w*w[3*NEXP+e];
    }
    float m = acc[0];
    #pragma unroll
    for(int e=1;e<NEXP;e++) m = fmaxf(m, acc[e]);
    float p[NEXP]; float s = 0.f;
    #pragma unroll
    for(int e=0;e<NEXP;e++){ p[e] = expf(acc[e]-m); s += p[e]; }
    float inv = 1.f/s;
    #pragma unroll
    for(int e=0;e<NEXP;e++) p[e] *= inv;

    int i0 = 0;
    #pragma unroll
    for(int e=1;e<NEXP;e++) if(p[e] > p[i0]) i0 = e;
    int i1 = -1;
    #pragma unroll
    for(int e=0;e<NEXP;e++) if(e != i0 && (i1 < 0 || p[e] > p[i1])) i1 = e;

    g_ti[2*n]   = i0;  g_ti[2*n+1]   = i1;
    g_tw[2*n]   = p[i0]; g_tw[2*n+1] = p[i1];
    g_slot[2*n] = -1;  g_slot[2*n+1] = -1;

    #pragma unroll
    for(int e=0;e<NEXP;e++){
        float v = p[e];
        for(int off=16; off; off >>= 1) v += __shfl_down_sync(0xffffffffu, v, off);
        if((tid & 31) == 0) atomicAdd(&sPS[e], v);
    }
    __syncthreads();
    if(tid < NEXP) g_pspart[blockIdx.x*NEXP + tid] = sPS[tid];
}

// ---------------- per-expert capacity scan (ballot-based) ----------------
__global__ void __launch_bounds__(256) scan_kernel(){
    const int e = blockIdx.x;
    const int tid = threadIdx.x;
    const int lane = tid & 31, w = tid >> 5;
    __shared__ int wsum[8];
    int base = 0;
    for(int c = 0; c < N_TOK/256; c++){
        int n = c*256 + tid;
        int i0 = g_ti[2*n], i1 = g_ti[2*n+1];
        int kk = (i0 == e) ? 0 : ((i1 == e) ? 1 : -1);
        int flag = (kk >= 0) ? 1 : 0;
        unsigned bal = __ballot_sync(0xffffffffu, flag);
        int pre = __popc(bal & ((1u << lane) - 1u));
        if(lane == 0) wsum[w] = __popc(bal);
        __syncthreads();
        int woff = 0, ctot = 0;
        #pragma unroll
        for(int q=0;q<8;q++){
            int v = wsum[q];
            if(q < w) woff += v;
            ctot += v;
        }
        int pos = base + woff + pre;
        if(flag && pos < CAP){
            g_sel[e*CAP + pos] = n;
            g_slot[2*n + kk] = e*CAP + pos;
        }
        base += ctot;
        __syncthreads();
    }
    int cnt = min(base, CAP);
    if(tid == 0){ g_cnt[e] = cnt; g_counts[e] = base; }
    for(int i = cnt + tid; i < CAP; i += 256) g_sel[e*CAP + i] = 0;
}

// ---------------- prep: gather x -> fp16 + convert W1,W2 -> fp16 (fused) ----------------
__global__ void __launch_bounds__(256) prep_kernel(const float* __restrict__ x,
                                                   const float4* __restrict__ W1,
                                                   const float4* __restrict__ W2){
    const int b = blockIdx.x;
    const int tid = threadIdx.x;
    if(b < 8192){
        const int e  = b >> 10;            // 1024 blocks per expert
        const int rg = b & 1023;           // row group (8 rows)
        const int rup = (g_cnt[e] + 255) & ~255;
        if(rg*8 >= rup) return;
        #pragma unroll
        for(int i=0;i<8;i++){
            int flat = tid + i*256;        // 2048 float4 chunks
            int r  = rg*8 + (flat >> 8);
            int c4 = flat & 255;
            const int src = g_sel[e*CAP + r];
            float4 v = reinterpret_cast<const float4*>(x + (size_t)src*DIM)[c4];
            __half2* d = reinterpret_cast<__half2*>(g_xg + ((size_t)e*CAP + r)*DIM) + 2*c4;
            d[0] = __floats2half2_rn(v.x, v.y);
            d[1] = __floats2half2_rn(v.z, v.w);
        }
    }else{
        const int which = (b < 16384) ? 0 : 1;
        const int b2 = b - (which ? 16384 : 8192);
        const float4* src = which ? W2 : W1;
        __half2* dst = reinterpret_cast<__half2*>(which ? g_W2h : g_W1h);
        const int i0 = b2*256 + tid;
        #pragma unroll
        for(int j=0;j<4;j++){
            int i = i0 + j*(8192*256);
            float4 v = src[i];
            dst[2*i]   = __floats2half2_rn(v.x, v.y);
            dst[2*i+1] = __floats2half2_rn(v.z, v.w);
        }
    }
}

// ---------------- HMMA grouped GEMM: 512 threads, 16 warps, warp tile 64x32 ----------------
// BM=256, BN=128, BK=32, 4-stage cp.async. wm = wid&3 (rows), wn = wid>>2 (cols).
template<int KDIM, int NDIM, int LAYER>
__global__ void __launch_bounds__(512,1) gemm_hmma(const float* __restrict__ bias){
    constexpr int BM = 256, BN = 128, BK = 32, STAGES = 4;
    constexpr int KT = KDIM / BK;
    constexpr int ASTR = BK + 8;                 // 40 halves
    constexpr int BSTR = BN + 8;                 // 136 halves
    constexpr int ABYTES = BM*ASTR*2;            // 20480
    constexpr int BBYTES = BK*BSTR*2;            // 8704
    constexpr int SBYTES = ABYTES + BBYTES;      // 29184

    const int e  = blockIdx.z;
    const int m0 = blockIdx.y * BM;
    const int n0 = blockIdx.x * BN;
    if(m0 >= g_cnt[e]) return;

    extern __shared__ char smem[];
    const uint32_t base = (uint32_t)__cvta_generic_to_shared(smem);

    const int tid  = threadIdx.x;
    const int wid  = tid >> 5, lane = tid & 31;
    const int wm   = wid & 3, wn = wid >> 2;     // wm 0..3 (64 rows), wn 0..3 (32 cols)
    const int lrow = lane & 15, lcol8 = (lane >> 4) * 8;
    // ldmB4t addressing
    const int bq = lane >> 3, bj = lane & 7;
    const int brow = (bq & 1)*8 + bj;            // k within 16
    const int bcol = (bq >> 1)*8;                // n within 16

    const __half* __restrict__ Aexp =
        ((LAYER == 1) ? g_xg : g_hbuf) + ((size_t)e*CAP + m0)*KDIM;
    const __half* __restrict__ Bexp =
        ((LAYER == 1) ? g_W1h : g_W2h) + (size_t)e*KDIM*NDIM + n0;

    auto loadStage = [&](int s, int kb){
        const uint32_t sa = base + s*SBYTES;
        // A: 1024 16B-chunks over 512 threads
        #pragma unroll
        for(int p=0;p<2;p++){
            int idx = tid + p*512;
            int r = idx >> 2, c = (idx & 3) * 8;
            cp16(sa + (r*ASTR + c)*2, Aexp + (size_t)r*KDIM + kb*BK + c);
        }
        // B: 512 16B-chunks
        {
            int r = tid >> 4, c = (tid & 15) * 8;
            cp16(sa + ABYTES + (r*BSTR + c)*2, Bexp + (size_t)(kb*BK + r)*NDIM + c);
        }
    };

    float acc[4][4][4];
    #pragma unroll
    for(int mi=0;mi<4;mi++)
        #pragma unroll
        for(int ni=0;ni<4;ni++)
            #pragma unroll
            for(int q=0;q<4;q++) acc[mi][ni][q] = 0.f;

    #pragma unroll
    for(int s=0;s<STAGES-1;s++){ loadStage(s, s); cp_commit(); }

    for(int kt = 0; kt < KT; kt++){
        cp_wait<STAGES-2>();
        __syncthreads();
        if(kt + STAGES-1 < KT) loadStage((kt + STAGES-1) & (STAGES-1), kt + STAGES-1);
        cp_commit();

        const uint32_t sa = base + (kt & (STAGES-1))*SBYTES;
        #pragma unroll
        for(int ks=0;ks<2;ks++){
            uint32_t a[4][4], b[2][4];
            #pragma unroll
            for(int mi=0;mi<4;mi++)
                ldmA4(a[mi], sa + ((wm*64 + mi*16 + lrow)*ASTR + ks*16 + lcol8)*2);
            #pragma unroll
            for(int np=0;np<2;np++)
                ldmB4t(b[np], sa + ABYTES + ((ks*16 + brow)*BSTR + wn*32 + np*16 + bcol)*2);
            #pragma unroll
            for(int mi=0;mi<4;mi++)
                #pragma unroll
                for(int np=0;np<2;np++){
                    mma16816(acc[mi][2*np],   a[mi], b[np][0], b[np][1]);
                    mma16816(acc[mi][2*np+1], a[mi], b[np][2], b[np][3]);
                }
        }
    }

    // epilogue
    const int g = lane >> 2;
    const int t = lane & 3;
    #pragma unroll
    for(int mi=0;mi<4;mi++){
        #pragma unroll
        for(int ni=0;ni<4;ni++){
            int col = n0 + wn*32 + ni*8 + t*2;
            float bv0 = __ldg(&bias[e*NDIM + col]);
            float bv1 = __ldg(&bias[e*NDIM + col + 1]);
            int r0 = m0 + wm*64 + mi*16 + g;
            int r1 = r0 + 8;
            if(LAYER == 1){
                __half2 v0 = __floats2half2_rn(fmaxf(acc[mi][ni][0]+bv0, 0.f),
                                               fmaxf(acc[mi][ni][1]+bv1, 0.f));
                __half2 v1 = __floats2half2_rn(fmaxf(acc[mi][ni][2]+bv0, 0.f),
                                               fmaxf(acc[mi][ni][3]+bv1, 0.f));
                *reinterpret_cast<__half2*>(&g_hbuf[((size_t)e*CAP + r0)*HID + col]) = v0;
                *reinterpret_cast<__half2*>(&g_hbuf[((size_t)e*CAP + r1)*HID + col]) = v1;
            }else{
                float2 v0 = make_float2(acc[mi][ni][0]+bv0, acc[mi][ni][1]+bv1);
                float2 v1 = make_float2(acc[mi][ni][2]+bv0, acc[mi][ni][3]+bv1);
                *reinterpret_cast<float2*>(&g_outs[((size_t)e*CAP + r0)*DIM + col]) = v0;
                *reinterpret_cast<float2*>(&g_outs[((size_t)e*CAP + r1)*DIM + col]) = v1;
            }
        }
    }
}

// ---------------- combine ----------------
__global__ void __launch_bounds__(256) combine_kernel(float* __restrict__ out){
    const int n = blockIdx.x;
    const int tid = threadIdx.x;
    int s0 = g_slot[2*n], s1 = g_slot[2*n+1];
    float w0 = g_tw[2*n], w1 = g_tw[2*n+1];
    if(s0 < 0){ w0 = 0.f; s0 = 0; }
    if(s1 < 0){ w1 = 0.f; s1 = 0; }
    const float4* r0 = reinterpret_cast<const float4*>(g_outs + (size_t)s0*DIM);
    const float4* r1 = reinterpret_cast<const float4*>(g_outs + (size_t)s1*DIM);
    float4 a = r0[tid];
    float4 b = r1[tid];
    float4 v;
    v.x = w0*a.x + w1*b.x;
    v.y = w0*a.y + w1*b.y;
    v.z = w0*a.z + w1*b.z;
    v.w = w0*a.w + w1*b.w;
    reinterpret_cast<float4*>(out + (size_t)n*DIM)[tid] = v;
}

// ---------------- aux loss ----------------
__global__ void aux_kernel(float* __restrict__ out, int out_size){
    __shared__ float ps[NEXP];
    const int tid = threadIdx.x;
    if(tid < NEXP){
        float s = 0.f;
        for(int b = 0; b < RBLK; b++) s += g_pspart[b*NEXP + tid];
        ps[tid] = s;
    }
    __syncthreads();
    if(tid == 0){
        float bal = 0.f, imp = 0.f;
        for(int e = 0; e < NEXP; e++){
            float density = ps[e] / (float)N_TOK;
            float usage   = (float)g_counts[e] / (float)N_TOK;
            bal += density * usage;
            imp += ps[e] * ps[e];
        }
        float aux = bal * (float)NEXP + imp / (float)NEXP;
        if(out_size > N_TOK*DIM) out[(size_t)N_TOK*DIM] = aux;
    }
}

// ---------------- launch ----------------
extern "C" void kernel_launch(void* const* d_in, const int* in_sizes, int n_in,
                              void* d_out, int out_size){
    const float* x  = (const float*)d_in[0];
    const float* Wr = (const float*)d_in[1];
    const float* br = (const float*)d_in[2];
    const float* W1 = (const float*)d_in[3];
    const float* b1 = (const float*)d_in[4];
    const float* W2 = (const float*)d_in[5];
    const float* b2 = (const float*)d_in[6];
    float* out = (float*)d_out;

    const int SMEM_BYTES = 4 * (256*40*2 + 32*136*2);  // 116736
    cudaFuncSetAttribute(gemm_hmma<DIM, HID, 1>, cudaFuncAttributeMaxDynamicSharedMemorySize, SMEM_BYTES);
    cudaFuncSetAttribute(gemm_hmma<HID, DIM, 2>, cudaFuncAttributeMaxDynamicSharedMemorySize, SMEM_BYTES);

    router_kernel<<<RBLK, 256>>>(x, Wr, br);
    scan_kernel<<<NEXP, 256>>>();
    prep_kernel<<<24576, 256>>>(x, (const float4*)W1, (const float4*)W2);
    gemm_hmma<DIM, HID, 1><<<dim3(HID/128, CAP/256, NEXP), 512, SMEM_BYTES>>>(b1);
    gemm_hmma<HID, DIM, 2><<<dim3(DIM/128, CAP/256, NEXP), 512, SMEM_BYTES>>>(b2);
    combine_kernel<<<N_TOK, 256>>>(out);
    aux_kernel<<<1, 32>>>(out, out_size);
}